// round 15
// baseline (speedup 1.0000x reference)
#include <cuda_runtime.h>
#include <cuda_fp16.h>
#include <cstdint>
#include <cstddef>

#define BB 16
#define HH 128
#define WW 128
#define SS 512

__device__ float d_s[BB * 128];
__device__ float d_q[128 * 128];
__device__ float d_dc[BB * 128];
__device__ __align__(16) __half d_U[BB * 16 * 128 * 136];  // [b][p][co][136]

__device__ __forceinline__ uint32_t smem_u32(const void* p) {
    uint32_t a;
    asm("{ .reg .u64 t; cvta.to.shared.u64 t, %1; cvt.u32.u64 %0, t; }" : "=r"(a) : "l"(p));
    return a;
}
__device__ __forceinline__ uint32_t h2_u32(__half2 h) {
    union { __half2 h2; uint32_t u; } cv;
    cv.h2 = h;
    return cv.u;
}
#define LDSM4(r, a) \
    asm volatile("ldmatrix.sync.aligned.m8n8.x4.shared.b16 {%0,%1,%2,%3}, [%4];" \
        : "=r"((r)[0]), "=r"((r)[1]), "=r"((r)[2]), "=r"((r)[3]) : "r"(a))
#define LDSM4T(r, a) \
    asm volatile("ldmatrix.sync.aligned.m8n8.x4.trans.shared.b16 {%0,%1,%2,%3}, [%4];" \
        : "=r"((r)[0]), "=r"((r)[1]), "=r"((r)[2]), "=r"((r)[3]) : "r"(a))
__device__ __forceinline__ void mma16816(float* c, const uint32_t* a, uint32_t b0, uint32_t b1) {
    asm volatile(
        "mma.sync.aligned.m16n8k16.row.col.f32.f16.f16.f32 "
        "{%0,%1,%2,%3}, {%4,%5,%6,%7}, {%8,%9}, {%0,%1,%2,%3};"
        : "+f"(c[0]), "+f"(c[1]), "+f"(c[2]), "+f"(c[3])
        : "r"(a[0]), "r"(a[1]), "r"(a[2]), "r"(a[3]), "r"(b0), "r"(b1));
}
#define CP_ASYNC16(dst, src) \
    asm volatile("cp.async.cg.shared.global [%0], [%1], 16;" :: "r"(dst), "l"(src))
#define CP_COMMIT() asm volatile("cp.async.commit_group;" ::: "memory")
#define CP_WAIT0()  asm volatile("cp.async.wait_group 0;" ::: "memory")

// ---------------- prep ----------------
__global__ void k_style(const float* __restrict__ style, const float* __restrict__ mod_w,
                        const float* __restrict__ mod_b) {
    int task = blockIdx.x * 8 + (threadIdx.x >> 5), lane = threadIdx.x & 31;
    int b = task >> 7, ci = task & 127;
    const float* st = style + b * SS;
    const float* mw = mod_w + ci * SS;
    float a = 0.f;
    for (int i = lane; i < SS; i += 32) a += st[i] * mw[i];
#pragma unroll
    for (int o = 16; o; o >>= 1) a += __shfl_xor_sync(0xffffffffu, a, o);
    if (lane == 0) d_s[task] = a + mod_b[ci];
}
__global__ void k_q(const float* __restrict__ weight) {
    int i = blockIdx.x * 256 + threadIdx.x;
    const float* w = weight + (size_t)i * 9;
    float s = 0.f;
#pragma unroll
    for (int k = 0; k < 9; k++) { float v = w[k]; s += v * v; }
    d_q[i] = s;
}
__global__ void k_dc() {
    int task = blockIdx.x * 8 + (threadIdx.x >> 5), lane = threadIdx.x & 31;
    int b = task >> 7, co = task & 127;
    float a = 0.f;
    for (int ci = lane; ci < 128; ci += 32) {
        float s = d_s[b * 128 + ci];
        a += d_q[co * 128 + ci] * s * s;
    }
#pragma unroll
    for (int o = 16; o; o >>= 1) a += __shfl_xor_sync(0xffffffffu, a, o);
    if (lane == 0) d_dc[task] = rsqrtf(a + 1e-8f);
}
// U = G (alpha g) G^T, fp16; grid (16,32) x 256
__global__ void k_uprep(const float* __restrict__ weight) {
    int b = blockIdx.x;
    int task = blockIdx.y * 256 + threadIdx.x;   // 8192 = 128co x 64 cipair
    int co = task >> 6, cp = task & 63;
    float U2[2][16];
#pragma unroll
    for (int e = 0; e < 2; e++) {
        int ci = cp * 2 + e;
        float al = d_s[b * 128 + ci] * d_dc[b * 128 + co];
        const float* g = weight + (size_t)(co * 128 + ci) * 9;
        float q[4][3];
#pragma unroll
        for (int c = 0; c < 3; c++) {
            float g0 = g[c] * al, g1 = g[3 + c] * al, g2 = g[6 + c] * al;
            q[0][c] = g0; q[1][c] = 0.5f * (g0 + g1 + g2);
            q[2][c] = 0.5f * (g0 - g1 + g2); q[3][c] = g2;
        }
#pragma unroll
        for (int u = 0; u < 4; u++) {
            U2[e][u * 4 + 0] = q[u][0];
            U2[e][u * 4 + 1] = 0.5f * (q[u][0] + q[u][1] + q[u][2]);
            U2[e][u * 4 + 2] = 0.5f * (q[u][0] - q[u][1] + q[u][2]);
            U2[e][u * 4 + 3] = q[u][2];
        }
    }
    __half2* base = (__half2*)d_U;
#pragma unroll
    for (int p = 0; p < 16; p++)
        base[(size_t)((b * 16 + p) * 128 + co) * 68 + cp] = __floats2half2_rn(U2[0][p], U2[1][p]);
}

// ---------------- fused Winograd conv ----------------
#define SM_V  0
#define SM_A0 131072
#define SM_A1 165888
#define SM_XT 131072
#define SMEM_BYTES 200704

__device__ __forceinline__ void prefA(uint32_t dst, const char* src, int tid) {
#pragma unroll
    for (int i = 0; i < 9; i++) {
        int e = i * 256 + tid;
        if (e < 2176) CP_ASYNC16(dst + (uint32_t)e * 16, src + (size_t)e * 16);
    }
    CP_COMMIT();
}

__global__ void __launch_bounds__(256) k_conv(const float* __restrict__ x,
                                              float* __restrict__ out) {
    extern __shared__ char smem[];
    uint32_t sb = smem_u32(smem);
    const int tid = threadIdx.x, wid = tid >> 5, lane = tid & 31;
    const int w0 = blockIdx.x * 16, h0 = blockIdx.y * 8, b = blockIdx.z;
    const int m0w = (wid & 3) * 32, n0w = (wid >> 2) * 16;
    const float* xb = x + (size_t)b * 128 * HH * WW;

    // phase 1: stage x -> xt [ci][10 rows][24 halfs (48B)]
#pragma unroll
    for (int i = 0; i < 30; i++) {
        int task = i * 256 + tid;               // 7680 = 128 x 10 x 6
        int ci = task / 60, rem = task - ci * 60;
        int r = rem / 6, c6 = rem - r * 6;
        int h = h0 - 1 + r, wc = w0 - 4 + c6 * 4;
        float4 v = make_float4(0.f, 0.f, 0.f, 0.f);
        if (h >= 0 && h < HH) {
            const float* row = xb + ((size_t)ci * HH + h) * WW;
            if (wc >= 0 && wc <= WW - 4) v = *(const float4*)(row + wc);
            else {
                if (wc + 0 >= 0 && wc + 0 < WW) v.x = row[wc + 0];
                if (wc + 1 >= 0 && wc + 1 < WW) v.y = row[wc + 1];
                if (wc + 2 >= 0 && wc + 2 < WW) v.z = row[wc + 2];
                if (wc + 3 >= 0 && wc + 3 < WW) v.w = row[wc + 3];
            }
        }
        uint32_t h01 = h2_u32(__floats2half2_rn(v.x, v.y));
        uint32_t h23 = h2_u32(__floats2half2_rn(v.z, v.w));
        uint32_t a = sb + SM_XT + (uint32_t)(ci * 480 + r * 48 + c6 * 8);
        asm volatile("st.shared.v2.b32 [%0], {%1,%2};" :: "r"(a), "r"(h01), "r"(h23));
    }
    __syncthreads();

    // phase 2: V[p][ci][t], 64B rows, chunk swizzle (t>>3)^((ci>>1)&3)
#pragma unroll
    for (int i = 0; i < 16; i++) {
        int task = i * 256 + tid;               // 4096 = 128ci x 32t
        int ci = task >> 5, t = task & 31;
        int th = t >> 3, tw = t & 7;
        uint32_t xbase = sb + SM_XT + (uint32_t)(ci * 480 + 2 * th * 48 + (2 * tw + 3) * 2);
        float d[4][4];
#pragma unroll
        for (int r4 = 0; r4 < 4; r4++)
#pragma unroll
            for (int c = 0; c < 4; c++) {
                unsigned short us;
                asm volatile("ld.shared.u16 %0, [%1];"
                             : "=h"(us) : "r"(xbase + (uint32_t)(r4 * 48 + c * 2)));
                d[r4][c] = __half2float(__ushort_as_half(us));
            }
        float e[4][4];
#pragma unroll
        for (int c = 0; c < 4; c++) {
            e[0][c] = d[0][c] - d[2][c]; e[1][c] = d[1][c] + d[2][c];
            e[2][c] = d[2][c] - d[1][c]; e[3][c] = d[1][c] - d[3][c];
        }
        uint32_t vdst = sb + SM_V + (uint32_t)(ci * 64 + ((th ^ ((ci >> 1) & 3)) << 4) + (t & 7) * 2);
#pragma unroll
        for (int u = 0; u < 4; u++) {
            float v0 = e[u][0] - e[u][2], v1 = e[u][1] + e[u][2];
            float v2 = e[u][2] - e[u][1], v3 = e[u][1] - e[u][3];
            unsigned short s0 = __half_as_ushort(__float2half_rn(v0));
            unsigned short s1 = __half_as_ushort(__float2half_rn(v1));
            unsigned short s2 = __half_as_ushort(__float2half_rn(v2));
            unsigned short s3 = __half_as_ushort(__float2half_rn(v3));
            asm volatile("st.shared.b16 [%0], %1;" :: "r"(vdst + (u * 4 + 0) * 8192u), "h"(s0));
            asm volatile("st.shared.b16 [%0], %1;" :: "r"(vdst + (u * 4 + 1) * 8192u), "h"(s1));
            asm volatile("st.shared.b16 [%0], %1;" :: "r"(vdst + (u * 4 + 2) * 8192u), "h"(s2));
            asm volatile("st.shared.b16 [%0], %1;" :: "r"(vdst + (u * 4 + 3) * 8192u), "h"(s3));
        }
    }
    __syncthreads();

    // phase 3: 16 position GEMMs, A double-buffered
    const char* Ub = (const char*)d_U + (size_t)(b * 16) * 34816;
    prefA(sb + SM_A0, Ub, tid);
    const uint32_t arow = (uint32_t)(m0w + (lane & 15)) * 272 + (uint32_t)(lane >> 4) * 16;
    const int rr = lane & 15;
    const uint32_t vsw = (uint32_t)(((n0w >> 3) + (lane >> 4)) ^ ((rr >> 1) & 3));
    const uint32_t vbase = sb + SM_V + (uint32_t)rr * 64 + vsw * 16;

    float oacc[4][16];
#pragma unroll
    for (int i = 0; i < 4; i++)
#pragma unroll
        for (int k = 0; k < 16; k++) oacc[i][k] = 0.f;
    const float At0[4] = {1.f, 1.f, 1.f, 0.f};
    const float At1[4] = {0.f, 1.f, -1.f, -1.f};

    for (int p = 0; p < 16; p++) {
        CP_WAIT0();
        __syncthreads();
        if (p < 15) prefA(sb + (((p + 1) & 1) ? SM_A1 : SM_A0), Ub + (size_t)(p + 1) * 34816, tid);
        uint32_t ab = sb + ((p & 1) ? SM_A1 : SM_A0) + arow;
        uint32_t vb = vbase + (uint32_t)p * 8192;
        float g[4][4];
#pragma unroll
        for (int i = 0; i < 4; i++)
#pragma unroll
            for (int k = 0; k < 4; k++) g[i][k] = 0.f;
#pragma unroll
        for (int ks = 0; ks < 8; ks++) {
            uint32_t a0[4], a1[4], bf[4];
            LDSM4(a0, ab + (uint32_t)ks * 32);
            LDSM4(a1, ab + (uint32_t)ks * 32 + 16u * 272u);
            LDSM4T(bf, vb + (uint32_t)ks * 1024);
            mma16816(g[0], a0, bf[0], bf[1]);
            mma16816(g[1], a0, bf[2], bf[3]);
            mma16816(g[2], a1, bf[0], bf[1]);
            mma16816(g[3], a1, bf[2], bf[3]);
        }
        int u = p >> 2, v = p & 3;
        float c00 = At0[u] * At0[v], c01 = At0[u] * At1[v];
        float c10 = At1[u] * At0[v], c11 = At1[u] * At1[v];
        float cf[4] = {c00, c01, c10, c11};
#pragma unroll
        for (int oi = 0; oi < 4; oi++) {
            float c = cf[oi];
            if (c != 0.f)
#pragma unroll
                for (int k = 0; k < 16; k++) oacc[oi][k] += c * (&g[0][0])[k];
        }
    }

    // epilogue: scatter 2x2 outputs per tile
#pragma unroll
    for (int mt = 0; mt < 2; mt++)
#pragma unroll
        for (int nk = 0; nk < 2; nk++)
#pragma unroll
            for (int q = 0; q < 4; q++) {
                int row = m0w + mt * 16 + (lane >> 2) + ((q >> 1) << 3);
                int n = n0w + nk * 8 + (lane & 3) * 2 + (q & 1);
                int th = n >> 3, tw = n & 7;
                int k = mt * 8 + nk * 4 + q;
#pragma unroll
                for (int i = 0; i < 2; i++)
#pragma unroll
                    for (int j = 0; j < 2; j++)
                        out[(((size_t)b * 128 + row) * HH + (h0 + 2 * th + i)) * WW
                            + (w0 + 2 * tw + j)] = oacc[i * 2 + j][k];
            }
}

// ---------------- launch ----------------
extern "C" void kernel_launch(void* const* d_in, const int* in_sizes, int n_in,
                              void* d_out, int out_size) {
    const float* x      = (const float*)d_in[0];
    const float* style  = (const float*)d_in[1];
    const float* weight = (const float*)d_in[2];
    const float* mod_w  = (const float*)d_in[3];
    const float* mod_b  = (const float*)d_in[4];
    float* out = (float*)d_out;

    cudaFuncSetAttribute(k_conv, cudaFuncAttributeMaxDynamicSharedMemorySize, SMEM_BYTES);

    k_style<<<256, 256>>>(style, mod_w, mod_b);
    k_q<<<64, 256>>>(weight);
    k_dc<<<256, 256>>>();
    k_uprep<<<dim3(16, 32), 256>>>(weight);
    dim3 grid(8, 16, 16);
    k_conv<<<grid, 256, SMEM_BYTES>>>(x, out);
}